// round 1
// baseline (speedup 1.0000x reference)
#include <cuda_runtime.h>
#include <cuda_bf16.h>
#include <float.h>
#include <math.h>

#define DMAX 64
#define NMAX 100000
#define GMAX 512

// ---------------- scratch (no allocations allowed) ----------------
__device__ float g_hws[NMAX * DMAX];   // dinv[src]-scaled conv output
__device__ float g_scat[NMAX * DMAX];  // scatter accumulator
__device__ float g_h[NMAX * DMAX];     // hidden state between layers
__device__ float g_dinv[NMAX];
__device__ int   g_cnt[NMAX];
__device__ float g_bnsum[DMAX], g_bnsumsq[DMAX];
__device__ float g_bnscale[DMAX], g_bnshift[DMAX];
__device__ int   g_gcnt[GMAX];
__device__ int   g_goff[GMAX];
__device__ float g_z[GMAX * 3 * DMAX];

// ---------------- helpers ----------------
__device__ __forceinline__ void red_add_f4(float4* addr, float4 v) {
    asm volatile("red.global.add.v4.f32 [%0], {%1,%2,%3,%4};"
                 :: "l"(addr), "f"(v.x), "f"(v.y), "f"(v.z), "f"(v.w)
                 : "memory");
}

__device__ __forceinline__ float gelu_exact(float x) {
    return 0.5f * x * (1.0f + erff(x * 0.70710678118654752f));
}

// ---------------- zero kernels ----------------
__global__ void zero_f4(float4* p, int n4) {
    int i = blockIdx.x * blockDim.x + threadIdx.x;
    if (i < n4) p[i] = make_float4(0.f, 0.f, 0.f, 0.f);
}
__global__ void zero_int(int* p, int n) {
    int i = blockIdx.x * blockDim.x + threadIdx.x;
    if (i < n) p[i] = 0;
}
__global__ void zero_bnsums() {
    int t = threadIdx.x;
    if (t < DMAX) { g_bnsum[t] = 0.f; g_bnsumsq[t] = 0.f; }
}

// ---------------- degree / dinv ----------------
__global__ void hist_edges(const int* __restrict__ ei, int E) {
    int e = blockIdx.x * blockDim.x + threadIdx.x;
    if (e < E) atomicAdd(&g_cnt[ei[E + e]], 1);   // dst row
}
__global__ void dinv_kernel(int n) {
    int i = blockIdx.x * blockDim.x + threadIdx.x;
    if (i < n) g_dinv[i] = rsqrtf((float)(g_cnt[i] + 1));  // +1 self-loop
}

// ---------------- graph histogram + scan ----------------
__global__ void hist_batch(const int* __restrict__ batch, int n) {
    int i = blockIdx.x * blockDim.x + threadIdx.x;
    if (i < n) atomicAdd(&g_gcnt[batch[i]], 1);
}
__global__ void scan_goff() {
    __shared__ int sh[GMAX];
    int t = threadIdx.x;
    sh[t] = g_gcnt[t];
    __syncthreads();
    for (int o = 1; o < GMAX; o <<= 1) {
        int u = (t >= o) ? sh[t - o] : 0;
        __syncthreads();
        sh[t] += u;
        __syncthreads();
    }
    g_goff[t] = sh[t] - g_gcnt[t];   // exclusive
}

// ---------------- GEMM: out[n,c] = dinv[n] * sum_k H[n,k] W[k,c] ----------------
__global__ void gemm_scaled(const float* __restrict__ H, const float* __restrict__ W,
                            float* __restrict__ out, int n) {
    __shared__ float Ws[64 * 64];
    __shared__ float Hs[32][64];
    int t = threadIdx.x;
    for (int i = t; i < 1024; i += 256)
        ((float4*)Ws)[i] = ((const float4*)W)[i];
    int row0 = blockIdx.x * 32;
    for (int i = t; i < 512; i += 256) {
        int r = i >> 4, q = i & 15;
        int row = row0 + r;
        float4 v = (row < n) ? ((const float4*)H)[row * 16 + q]
                             : make_float4(0.f, 0.f, 0.f, 0.f);
        ((float4*)Hs[r])[q] = v;
    }
    __syncthreads();
    int c = t & 63, rb = (t >> 6) * 8;
    float acc[8];
#pragma unroll
    for (int i = 0; i < 8; i++) acc[i] = 0.f;
#pragma unroll
    for (int k = 0; k < 64; k++) {
        float w = Ws[k * 64 + c];
#pragma unroll
        for (int i = 0; i < 8; i++) acc[i] = fmaf(Hs[rb + i][k], w, acc[i]);
    }
#pragma unroll
    for (int i = 0; i < 8; i++) {
        int row = row0 + rb + i;
        if (row < n) out[row * 64 + c] = acc[i] * g_dinv[row];
    }
}

// ---------------- edge scatter: scat[dst] += hws[src] ----------------
__global__ void scatter_edges(const int* __restrict__ ei, int E) {
    long long idx = (long long)blockIdx.x * blockDim.x + threadIdx.x;
    if (idx >= (long long)E * 16) return;
    int e = (int)(idx >> 4), q = (int)(idx & 15);
    int s = ei[e], d = ei[E + e];
    float4 v = ((const float4*)g_hws)[s * 16 + q];
    red_add_f4(&((float4*)g_scat)[d * 16 + q], v);
}

// ---------------- batchnorm stat reduce ----------------
__global__ void bn_reduce(const float* __restrict__ convB, int n) {
    int d = threadIdx.x & 63;
    int lane = threadIdx.x >> 6;     // 0..3
    float cb = convB[d];
    float s = 0.f, s2 = 0.f;
    for (int r = blockIdx.x * 4 + lane; r < n; r += gridDim.x * 4) {
        float pre = g_dinv[r] * (g_scat[r * 64 + d] + g_hws[r * 64 + d]) + cb;
        s += pre; s2 += pre * pre;
    }
    __shared__ float sha[4][64], shb[4][64];
    sha[lane][d] = s; shb[lane][d] = s2;
    __syncthreads();
    if (lane == 0) {
        s  = sha[0][d] + sha[1][d] + sha[2][d] + sha[3][d];
        s2 = shb[0][d] + shb[1][d] + shb[2][d] + shb[3][d];
        atomicAdd(&g_bnsum[d], s);
        atomicAdd(&g_bnsumsq[d], s2);
    }
}

__global__ void bn_final(const float* __restrict__ bng, const float* __restrict__ bnb,
                         float invN) {
    int d = threadIdx.x;
    float mu  = g_bnsum[d] * invN;
    float var = g_bnsumsq[d] * invN - mu * mu;
    float rstd = rsqrtf(var + 1e-5f);
    float sc = rstd * bng[d];
    g_bnscale[d] = sc;
    g_bnshift[d] = bnb[d] - mu * sc;
}

// ---------------- BN apply + residual + LayerNorm + GELU ----------------
__global__ void norm_act(const float* __restrict__ convB,
                         const float* __restrict__ lng, const float* __restrict__ lnb,
                         const float* __restrict__ xin,   // residual (null for layer 0)
                         float* __restrict__ hout, int n) {
    int r = (blockIdx.x * blockDim.x + threadIdx.x) >> 5;
    int lane = threadIdx.x & 31;
    if (r >= n) return;
    float di = g_dinv[r];
    int i0 = r * 64 + lane, i1 = i0 + 32;
    float v0 = di * (g_scat[i0] + g_hws[i0]) + convB[lane];
    float v1 = di * (g_scat[i1] + g_hws[i1]) + convB[lane + 32];
    v0 = v0 * g_bnscale[lane]      + g_bnshift[lane];
    v1 = v1 * g_bnscale[lane + 32] + g_bnshift[lane + 32];
    if (xin) { v0 += xin[i0]; v1 += xin[i1]; }
    float s = v0 + v1;
#pragma unroll
    for (int o = 16; o; o >>= 1) s += __shfl_xor_sync(0xffffffffu, s, o);
    float mu = s * (1.0f / 64.0f);
    float d0 = v0 - mu, d1 = v1 - mu;
    float vv = d0 * d0 + d1 * d1;
#pragma unroll
    for (int o = 16; o; o >>= 1) vv += __shfl_xor_sync(0xffffffffu, vv, o);
    float rstd = rsqrtf(vv * (1.0f / 64.0f) + 1e-5f);
    float y0 = d0 * rstd * lng[lane]      + lnb[lane];
    float y1 = d1 * rstd * lng[lane + 32] + lnb[lane + 32];
    hout[i0] = gelu_exact(y0);
    hout[i1] = gelu_exact(y1);
}

// ---------------- pooling (batch sorted -> contiguous segments) ----------------
__global__ void pool_graphs() {
    int g = blockIdx.x;
    int start = g_goff[g], cnt = g_gcnt[g];
    int d = threadIdx.x & 63, lane = threadIdx.x >> 6;
    float s = 0.f, m = -FLT_MAX;
    for (int r = start + lane; r < start + cnt; r += 4) {
        float v = g_h[r * 64 + d];
        s += v; m = fmaxf(m, v);
    }
    __shared__ float shs[4][64], shm[4][64];
    shs[lane][d] = s; shm[lane][d] = m;
    __syncthreads();
    if (lane == 0) {
        s = shs[0][d] + shs[1][d] + shs[2][d] + shs[3][d];
        m = fmaxf(fmaxf(shm[0][d], shm[1][d]), fmaxf(shm[2][d], shm[3][d]));
        float mean = (cnt > 0) ? s / (float)cnt : 0.f;
        if (cnt == 0) { m = 0.f; s = 0.f; }
        g_z[g * 192 + d]        = mean;
        g_z[g * 192 + 64 + d]   = m;
        g_z[g * 192 + 128 + d]  = s;
    }
}

// ---------------- fused MLP head: 192 -> 128 -> 64 -> 1 ----------------
__global__ void mlp_head(const float* __restrict__ W1, const float* __restrict__ b1,
                         const float* __restrict__ l1g, const float* __restrict__ l1b,
                         const float* __restrict__ W2, const float* __restrict__ b2,
                         const float* __restrict__ l2g, const float* __restrict__ l2b,
                         const float* __restrict__ W3, const float* __restrict__ b3,
                         float* __restrict__ out) {
    int g = blockIdx.x, t = threadIdx.x;   // 128 threads
    __shared__ float zs[192];
    __shared__ float s2[128];
    __shared__ float red[128];
    for (int i = t; i < 192; i += 128) zs[i] = g_z[g * 192 + i];
    __syncthreads();
    float acc = b1[t];
#pragma unroll 4
    for (int k = 0; k < 192; k++) acc = fmaf(zs[k], W1[k * 128 + t], acc);
    // LN over 128
    red[t] = acc; __syncthreads();
    for (int o = 64; o > 0; o >>= 1) { if (t < o) red[t] += red[t + o]; __syncthreads(); }
    float mu = red[0] * (1.0f / 128.0f); __syncthreads();
    float dv = acc - mu;
    red[t] = dv * dv; __syncthreads();
    for (int o = 64; o > 0; o >>= 1) { if (t < o) red[t] += red[t + o]; __syncthreads(); }
    float rstd = rsqrtf(red[0] * (1.0f / 128.0f) + 1e-5f); __syncthreads();
    float y = dv * rstd * l1g[t] + l1b[t];
    s2[t] = gelu_exact(y);
    __syncthreads();
    // layer 2: 128 -> 64
    float acc2 = 0.f;
    if (t < 64) {
        acc2 = b2[t];
#pragma unroll 4
        for (int k = 0; k < 128; k++) acc2 = fmaf(s2[k], W2[k * 64 + t], acc2);
    }
    red[t] = (t < 64) ? acc2 : 0.f; __syncthreads();
    for (int o = 64; o > 0; o >>= 1) { if (t < o) red[t] += red[t + o]; __syncthreads(); }
    float mu2 = red[0] * (1.0f / 64.0f); __syncthreads();
    float dv2 = acc2 - mu2;
    red[t] = (t < 64) ? dv2 * dv2 : 0.f; __syncthreads();
    for (int o = 64; o > 0; o >>= 1) { if (t < o) red[t] += red[t + o]; __syncthreads(); }
    float rstd2 = rsqrtf(red[0] * (1.0f / 64.0f) + 1e-5f); __syncthreads();
    float y2 = 0.f;
    if (t < 64) y2 = gelu_exact(dv2 * rstd2 * l2g[t] + l2b[t]);
    red[t] = (t < 64) ? y2 * W3[t] : 0.f; __syncthreads();
    for (int o = 64; o > 0; o >>= 1) { if (t < o) red[t] += red[t + o]; __syncthreads(); }
    if (t == 0) out[g] = red[0] + b3[0];
}

// ---------------- host ----------------
extern "C" void kernel_launch(void* const* d_in, const int* in_sizes, int n_in,
                              void* d_out, int out_size) {
    const float* x     = (const float*)d_in[0];
    const int*   ei    = (const int*)d_in[1];
    const int*   batch = (const int*)d_in[2];
    const float* convW = (const float*)d_in[3];
    const float* convB = (const float*)d_in[4];
    const float* bn_g  = (const float*)d_in[5];
    const float* bn_b  = (const float*)d_in[6];
    const float* ln_g  = (const float*)d_in[7];
    const float* ln_b  = (const float*)d_in[8];
    const float* W1    = (const float*)d_in[9];
    const float* b1    = (const float*)d_in[10];
    const float* l1g   = (const float*)d_in[11];
    const float* l1b   = (const float*)d_in[12];
    const float* W2    = (const float*)d_in[13];
    const float* b2    = (const float*)d_in[14];
    const float* l2g   = (const float*)d_in[15];
    const float* l2b   = (const float*)d_in[16];
    const float* W3    = (const float*)d_in[17];
    const float* b3    = (const float*)d_in[18];
    float* out = (float*)d_out;

    const int N = in_sizes[0] / 64;
    const int E = in_sizes[1] / 2;
    const int G = out_size;          // 512
    const int L = in_sizes[3] / (64 * 64);

    int* p_cnt; float* p_scat; float* p_h; int* p_gcnt; float* p_hws;
    cudaGetSymbolAddress((void**)&p_cnt,  g_cnt);
    cudaGetSymbolAddress((void**)&p_scat, g_scat);
    cudaGetSymbolAddress((void**)&p_h,    g_h);
    cudaGetSymbolAddress((void**)&p_gcnt, g_gcnt);
    cudaGetSymbolAddress((void**)&p_hws,  g_hws);

    const int TB = 256;
    // degrees -> dinv
    zero_int<<<(N + TB - 1) / TB, TB>>>(p_cnt, N);
    hist_edges<<<(E + TB - 1) / TB, TB>>>(ei, E);
    dinv_kernel<<<(N + TB - 1) / TB, TB>>>(N);
    // graph segment offsets
    zero_int<<<(G + TB - 1) / TB, TB>>>(p_gcnt, G);
    hist_batch<<<(N + TB - 1) / TB, TB>>>(batch, N);
    scan_goff<<<1, G>>>();

    long long scatThreads = (long long)E * 16;
    int scatBlocks = (int)((scatThreads + TB - 1) / TB);
    int n4 = N * 16;

    const float* h_cur = x;
    for (int i = 0; i < L; i++) {
        zero_f4<<<(n4 + TB - 1) / TB, TB>>>((float4*)p_scat, n4);
        zero_bnsums<<<1, 64>>>();
        gemm_scaled<<<(N + 31) / 32, 256>>>(h_cur, convW + i * 64 * 64, p_hws, N);
        scatter_edges<<<scatBlocks, TB>>>(ei, E);
        bn_reduce<<<512, 256>>>(convB + i * 64, N);
        bn_final<<<1, 64>>>(bn_g + i * 64, bn_b + i * 64, 1.0f / (float)N);
        const float* xin = (i == 0) ? (const float*)nullptr : (const float*)p_h;
        norm_act<<<(N * 32 + TB - 1) / TB, TB>>>(convB + i * 64, ln_g + i * 64,
                                                 ln_b + i * 64, xin, p_h, N);
        h_cur = p_h;
    }

    pool_graphs<<<G, 256>>>();
    mlp_head<<<G, 128>>>(W1, b1, l1g, l1b, W2, b2, l2g, l2b, W3, b3, out);
}

// round 2
// speedup vs baseline: 1.9451x; 1.9451x over previous
#include <cuda_runtime.h>
#include <cuda_bf16.h>
#include <float.h>
#include <math.h>

#define DMAX 64
#define NMAX 100000
#define EMAX 1600000
#define GMAX 512

// ---------------- scratch (no allocations allowed) ----------------
__device__ float g_hws[NMAX * DMAX];   // dinv[src]-scaled conv output
__device__ float g_pre[NMAX * DMAX];   // pre-BN aggregated values
__device__ float g_h[NMAX * DMAX];     // hidden state between layers
__device__ float g_dinv[NMAX];
__device__ int   g_cnt[NMAX];
__device__ int   g_incl[NMAX];
__device__ int   g_rowptr[NMAX + 1];
__device__ int   g_wpos[NMAX];
__device__ int   g_srcs[EMAX];
__device__ int   g_part[128];
__device__ float g_bnsum[DMAX], g_bnsumsq[DMAX];
__device__ float g_bnscale[DMAX], g_bnshift[DMAX];
__device__ int   g_gcnt[GMAX];
__device__ int   g_goff[GMAX];
__device__ float g_z[GMAX * 3 * DMAX];

// ---------------- helpers ----------------
__device__ __forceinline__ float gelu_exact(float x) {
    return 0.5f * x * (1.0f + erff(x * 0.70710678118654752f));
}

// ---------------- zero kernels ----------------
__global__ void zero_int(int* p, int n) {
    int i = blockIdx.x * blockDim.x + threadIdx.x;
    if (i < n) p[i] = 0;
}
__global__ void zero_bnsums() {
    int t = threadIdx.x;
    if (t < DMAX) { g_bnsum[t] = 0.f; g_bnsumsq[t] = 0.f; }
}

// ---------------- degree / dinv ----------------
__global__ void hist_edges(const int* __restrict__ ei, int E) {
    int e = blockIdx.x * blockDim.x + threadIdx.x;
    if (e < E) atomicAdd(&g_cnt[ei[E + e]], 1);   // dst row
}
__global__ void dinv_kernel(int n) {
    int i = blockIdx.x * blockDim.x + threadIdx.x;
    if (i < n) g_dinv[i] = rsqrtf((float)(g_cnt[i] + 1));  // +1 self-loop
}

// ---------------- CSR build: scan + place ----------------
__global__ void scan_blocks(int n) {
    __shared__ int sh[1024];
    int t = threadIdx.x;
    int i = blockIdx.x * 1024 + t;
    int v = (i < n) ? g_cnt[i] : 0;
    sh[t] = v;
    __syncthreads();
    for (int o = 1; o < 1024; o <<= 1) {
        int u = (t >= o) ? sh[t - o] : 0;
        __syncthreads();
        sh[t] += u;
        __syncthreads();
    }
    if (i < n) g_incl[i] = sh[t];
    if (t == 1023) g_part[blockIdx.x] = sh[1023];
}
__global__ void scan_partials(int nb) {
    __shared__ int sh[128];
    int t = threadIdx.x;
    int v = (t < nb) ? g_part[t] : 0;
    sh[t] = v;
    __syncthreads();
    for (int o = 1; o < 128; o <<= 1) {
        int u = (t >= o) ? sh[t - o] : 0;
        __syncthreads();
        sh[t] += u;
        __syncthreads();
    }
    g_part[t] = sh[t] - v;   // exclusive
}
__global__ void scan_finish(int n) {
    int i = blockIdx.x * 1024 + threadIdx.x;
    if (i < n) {
        int off = g_part[i >> 10];
        int incl = g_incl[i] + off;
        int rp = incl - g_cnt[i];
        g_rowptr[i] = rp;
        g_wpos[i]   = rp;
        if (i == n - 1) g_rowptr[n] = incl;
    }
}
__global__ void place_edges(const int* __restrict__ ei, int E) {
    int e = blockIdx.x * blockDim.x + threadIdx.x;
    if (e < E) {
        int s = ei[e], d = ei[E + e];
        int pos = atomicAdd(&g_wpos[d], 1);
        g_srcs[pos] = s;
    }
}

// ---------------- graph histogram + scan ----------------
__global__ void hist_batch(const int* __restrict__ batch, int n) {
    int i = blockIdx.x * blockDim.x + threadIdx.x;
    if (i < n) atomicAdd(&g_gcnt[batch[i]], 1);
}
__global__ void scan_goff() {
    __shared__ int sh[GMAX];
    int t = threadIdx.x;
    sh[t] = g_gcnt[t];
    __syncthreads();
    for (int o = 1; o < GMAX; o <<= 1) {
        int u = (t >= o) ? sh[t - o] : 0;
        __syncthreads();
        sh[t] += u;
        __syncthreads();
    }
    g_goff[t] = sh[t] - g_gcnt[t];   // exclusive
}

// ---------------- GEMM: hws[n,c] = dinv[n] * sum_k H[n,k] W[k,c] ----------------
__global__ __launch_bounds__(256) void gemm_scaled(const float* __restrict__ H,
                                                   const float* __restrict__ W,
                                                   float* __restrict__ out, int n) {
    __shared__ float Ws[64 * 64];      // [k][c]
    __shared__ float Hs[64][65];       // padded
    int t = threadIdx.x;
    for (int i = t; i < 1024; i += 256)
        ((float4*)Ws)[i] = ((const float4*)W)[i];
    int row0 = blockIdx.x * 64;
    for (int i = t; i < 1024; i += 256) {
        int r = i >> 4, q = i & 15;
        int row = row0 + r;
        float4 v = (row < n) ? __ldg(&((const float4*)H)[row * 16 + q])
                             : make_float4(0.f, 0.f, 0.f, 0.f);
        Hs[r][q * 4 + 0] = v.x;
        Hs[r][q * 4 + 1] = v.y;
        Hs[r][q * 4 + 2] = v.z;
        Hs[r][q * 4 + 3] = v.w;
    }
    __syncthreads();
    int cq = (t & 15) * 4;
    int rb = (t >> 4) * 4;
    float acc[4][4];
#pragma unroll
    for (int i = 0; i < 4; i++)
#pragma unroll
        for (int j = 0; j < 4; j++) acc[i][j] = 0.f;
#pragma unroll 8
    for (int k = 0; k < 64; k++) {
        float4 w = *(const float4*)&Ws[k * 64 + cq];
        float h0 = Hs[rb + 0][k];
        float h1 = Hs[rb + 1][k];
        float h2 = Hs[rb + 2][k];
        float h3 = Hs[rb + 3][k];
        acc[0][0] = fmaf(h0, w.x, acc[0][0]); acc[0][1] = fmaf(h0, w.y, acc[0][1]);
        acc[0][2] = fmaf(h0, w.z, acc[0][2]); acc[0][3] = fmaf(h0, w.w, acc[0][3]);
        acc[1][0] = fmaf(h1, w.x, acc[1][0]); acc[1][1] = fmaf(h1, w.y, acc[1][1]);
        acc[1][2] = fmaf(h1, w.z, acc[1][2]); acc[1][3] = fmaf(h1, w.w, acc[1][3]);
        acc[2][0] = fmaf(h2, w.x, acc[2][0]); acc[2][1] = fmaf(h2, w.y, acc[2][1]);
        acc[2][2] = fmaf(h2, w.z, acc[2][2]); acc[2][3] = fmaf(h2, w.w, acc[2][3]);
        acc[3][0] = fmaf(h3, w.x, acc[3][0]); acc[3][1] = fmaf(h3, w.y, acc[3][1]);
        acc[3][2] = fmaf(h3, w.z, acc[3][2]); acc[3][3] = fmaf(h3, w.w, acc[3][3]);
    }
#pragma unroll
    for (int i = 0; i < 4; i++) {
        int row = row0 + rb + i;
        if (row < n) {
            float di = g_dinv[row];
            float4 o;
            o.x = acc[i][0] * di; o.y = acc[i][1] * di;
            o.z = acc[i][2] * di; o.w = acc[i][3] * di;
            ((float4*)out)[row * 16 + (cq >> 2)] = o;
        }
    }
}

// ---------------- CSR aggregate + self-loop + dinv scale + convB + BN partials --
__global__ __launch_bounds__(512) void aggregate(const float* __restrict__ convB,
                                                 float invalid, int n) {
    __shared__ float bs[64], bs2[64];
    int t = threadIdx.x;
    if (t < 64) { bs[t] = 0.f; bs2[t] = 0.f; }
    __syncthreads();
    int r = (blockIdx.x * blockDim.x + t) >> 5;
    int lane = t & 31;
    if (r < n) {
        float a0 = g_hws[r * 64 + lane];        // self-loop term
        float a1 = g_hws[r * 64 + 32 + lane];
        int p0 = g_rowptr[r], p1 = g_rowptr[r + 1];
        for (int p = p0; p < p1; p++) {
            int s = g_srcs[p];
            a0 += g_hws[s * 64 + lane];
            a1 += g_hws[s * 64 + 32 + lane];
        }
        float di = g_dinv[r];
        float pre0 = fmaf(di, a0, convB[lane]);
        float pre1 = fmaf(di, a1, convB[lane + 32]);
        g_pre[r * 64 + lane]      = pre0;
        g_pre[r * 64 + 32 + lane] = pre1;
        atomicAdd(&bs[lane], pre0);
        atomicAdd(&bs[lane + 32], pre1);
        atomicAdd(&bs2[lane], pre0 * pre0);
        atomicAdd(&bs2[lane + 32], pre1 * pre1);
    }
    __syncthreads();
    if (t < 64) {
        atomicAdd(&g_bnsum[t], bs[t]);
        atomicAdd(&g_bnsumsq[t], bs2[t]);
    }
}

__global__ void bn_final(const float* __restrict__ bng, const float* __restrict__ bnb,
                         float invN) {
    int d = threadIdx.x;
    float mu  = g_bnsum[d] * invN;
    float var = g_bnsumsq[d] * invN - mu * mu;
    float rstd = rsqrtf(var + 1e-5f);
    float sc = rstd * bng[d];
    g_bnscale[d] = sc;
    g_bnshift[d] = bnb[d] - mu * sc;
}

// ---------------- BN apply + residual + LayerNorm + GELU ----------------
__global__ void norm_act(const float* __restrict__ lng, const float* __restrict__ lnb,
                         const float* __restrict__ xin,   // residual (null for layer 0)
                         float* __restrict__ hout, int n) {
    int r = (blockIdx.x * blockDim.x + threadIdx.x) >> 5;
    int lane = threadIdx.x & 31;
    if (r >= n) return;
    int i0 = r * 64 + lane, i1 = i0 + 32;
    float v0 = g_pre[i0] * g_bnscale[lane]      + g_bnshift[lane];
    float v1 = g_pre[i1] * g_bnscale[lane + 32] + g_bnshift[lane + 32];
    if (xin) { v0 += xin[i0]; v1 += xin[i1]; }
    float s = v0 + v1;
#pragma unroll
    for (int o = 16; o; o >>= 1) s += __shfl_xor_sync(0xffffffffu, s, o);
    float mu = s * (1.0f / 64.0f);
    float d0 = v0 - mu, d1 = v1 - mu;
    float vv = d0 * d0 + d1 * d1;
#pragma unroll
    for (int o = 16; o; o >>= 1) vv += __shfl_xor_sync(0xffffffffu, vv, o);
    float rstd = rsqrtf(vv * (1.0f / 64.0f) + 1e-5f);
    float y0 = d0 * rstd * lng[lane]      + lnb[lane];
    float y1 = d1 * rstd * lng[lane + 32] + lnb[lane + 32];
    hout[i0] = gelu_exact(y0);
    hout[i1] = gelu_exact(y1);
}

// ---------------- pooling (batch sorted -> contiguous segments) ----------------
__global__ void pool_graphs() {
    int g = blockIdx.x;
    int start = g_goff[g], cnt = g_gcnt[g];
    int d = threadIdx.x & 63, lane = threadIdx.x >> 6;
    float s = 0.f, m = -FLT_MAX;
    for (int r = start + lane; r < start + cnt; r += 4) {
        float v = g_h[r * 64 + d];
        s += v; m = fmaxf(m, v);
    }
    __shared__ float shs[4][64], shm[4][64];
    shs[lane][d] = s; shm[lane][d] = m;
    __syncthreads();
    if (lane == 0) {
        s = shs[0][d] + shs[1][d] + shs[2][d] + shs[3][d];
        m = fmaxf(fmaxf(shm[0][d], shm[1][d]), fmaxf(shm[2][d], shm[3][d]));
        float mean = (cnt > 0) ? s / (float)cnt : 0.f;
        if (cnt == 0) { m = 0.f; s = 0.f; }
        g_z[g * 192 + d]        = mean;
        g_z[g * 192 + 64 + d]   = m;
        g_z[g * 192 + 128 + d]  = s;
    }
}

// ---------------- fused MLP head: 192 -> 128 -> 64 -> 1 ----------------
__global__ void mlp_head(const float* __restrict__ W1, const float* __restrict__ b1,
                         const float* __restrict__ l1g, const float* __restrict__ l1b,
                         const float* __restrict__ W2, const float* __restrict__ b2,
                         const float* __restrict__ l2g, const float* __restrict__ l2b,
                         const float* __restrict__ W3, const float* __restrict__ b3,
                         float* __restrict__ out) {
    int g = blockIdx.x, t = threadIdx.x;   // 128 threads
    __shared__ float zs[192];
    __shared__ float s2[128];
    __shared__ float red[128];
    for (int i = t; i < 192; i += 128) zs[i] = g_z[g * 192 + i];
    __syncthreads();
    float acc = b1[t];
#pragma unroll 4
    for (int k = 0; k < 192; k++) acc = fmaf(zs[k], W1[k * 128 + t], acc);
    red[t] = acc; __syncthreads();
    for (int o = 64; o > 0; o >>= 1) { if (t < o) red[t] += red[t + o]; __syncthreads(); }
    float mu = red[0] * (1.0f / 128.0f); __syncthreads();
    float dv = acc - mu;
    red[t] = dv * dv; __syncthreads();
    for (int o = 64; o > 0; o >>= 1) { if (t < o) red[t] += red[t + o]; __syncthreads(); }
    float rstd = rsqrtf(red[0] * (1.0f / 128.0f) + 1e-5f); __syncthreads();
    float y = dv * rstd * l1g[t] + l1b[t];
    s2[t] = gelu_exact(y);
    __syncthreads();
    float acc2 = 0.f;
    if (t < 64) {
        acc2 = b2[t];
#pragma unroll 4
        for (int k = 0; k < 128; k++) acc2 = fmaf(s2[k], W2[k * 64 + t], acc2);
    }
    red[t] = (t < 64) ? acc2 : 0.f; __syncthreads();
    for (int o = 64; o > 0; o >>= 1) { if (t < o) red[t] += red[t + o]; __syncthreads(); }
    float mu2 = red[0] * (1.0f / 64.0f); __syncthreads();
    float dv2 = acc2 - mu2;
    red[t] = (t < 64) ? dv2 * dv2 : 0.f; __syncthreads();
    for (int o = 64; o > 0; o >>= 1) { if (t < o) red[t] += red[t + o]; __syncthreads(); }
    float rstd2 = rsqrtf(red[0] * (1.0f / 64.0f) + 1e-5f); __syncthreads();
    float y2 = 0.f;
    if (t < 64) y2 = gelu_exact(dv2 * rstd2 * l2g[t] + l2b[t]);
    red[t] = (t < 64) ? y2 * W3[t] : 0.f; __syncthreads();
    for (int o = 64; o > 0; o >>= 1) { if (t < o) red[t] += red[t + o]; __syncthreads(); }
    if (t == 0) out[g] = red[0] + b3[0];
}

// ---------------- host ----------------
extern "C" void kernel_launch(void* const* d_in, const int* in_sizes, int n_in,
                              void* d_out, int out_size) {
    const float* x     = (const float*)d_in[0];
    const int*   ei    = (const int*)d_in[1];
    const int*   batch = (const int*)d_in[2];
    const float* convW = (const float*)d_in[3];
    const float* convB = (const float*)d_in[4];
    const float* bn_g  = (const float*)d_in[5];
    const float* bn_b  = (const float*)d_in[6];
    const float* ln_g  = (const float*)d_in[7];
    const float* ln_b  = (const float*)d_in[8];
    const float* W1    = (const float*)d_in[9];
    const float* b1    = (const float*)d_in[10];
    const float* l1g   = (const float*)d_in[11];
    const float* l1b   = (const float*)d_in[12];
    const float* W2    = (const float*)d_in[13];
    const float* b2    = (const float*)d_in[14];
    const float* l2g   = (const float*)d_in[15];
    const float* l2b   = (const float*)d_in[16];
    const float* W3    = (const float*)d_in[17];
    const float* b3    = (const float*)d_in[18];
    float* out = (float*)d_out;

    const int N = in_sizes[0] / 64;
    const int E = in_sizes[1] / 2;
    const int G = out_size;          // 512
    const int L = in_sizes[3] / (64 * 64);

    int* p_cnt; int* p_gcnt; float* p_hws; float* p_h;
    cudaGetSymbolAddress((void**)&p_cnt,  g_cnt);
    cudaGetSymbolAddress((void**)&p_gcnt, g_gcnt);
    cudaGetSymbolAddress((void**)&p_hws,  g_hws);
    cudaGetSymbolAddress((void**)&p_h,    g_h);

    const int TB = 256;
    // degrees -> dinv, then CSR
    zero_int<<<(N + TB - 1) / TB, TB>>>(p_cnt, N);
    hist_edges<<<(E + TB - 1) / TB, TB>>>(ei, E);
    dinv_kernel<<<(N + TB - 1) / TB, TB>>>(N);
    int nb = (N + 1023) / 1024;
    scan_blocks<<<nb, 1024>>>(N);
    scan_partials<<<1, 128>>>(nb);
    scan_finish<<<nb, 1024>>>(N);
    place_edges<<<(E + TB - 1) / TB, TB>>>(ei, E);

    // graph segment offsets
    zero_int<<<(G + TB - 1) / TB, TB>>>(p_gcnt, G);
    hist_batch<<<(N + TB - 1) / TB, TB>>>(batch, N);
    scan_goff<<<1, G>>>();

    const float* h_cur = x;
    for (int i = 0; i < L; i++) {
        zero_bnsums<<<1, 64>>>();
        gemm_scaled<<<(N + 63) / 64, 256>>>(h_cur, convW + i * 64 * 64, p_hws, N);
        aggregate<<<(N * 32 + 511) / 512, 512>>>(convB + i * 64, 0.f, N);
        bn_final<<<1, 64>>>(bn_g + i * 64, bn_b + i * 64, 1.0f / (float)N);
        const float* xin = (i == 0) ? (const float*)nullptr : (const float*)p_h;
        norm_act<<<(N * 32 + TB - 1) / TB, TB>>>(ln_g + i * 64, ln_b + i * 64,
                                                 xin, p_h, N);
        h_cur = p_h;
    }

    pool_graphs<<<G, 256>>>();
    mlp_head<<<G, 128>>>(W1, b1, l1g, l1b, W2, b2, l2g, l2b, W3, b3, out);
}

// round 4
// speedup vs baseline: 2.0018x; 1.0291x over previous
#include <cuda_runtime.h>
#include <cuda_fp16.h>
#include <float.h>
#include <math.h>

#define DMAX 64
#define NMAX 100000
#define EMAX 1600000
#define GMAX 512

// ---------------- scratch (no allocations allowed) ----------------
__device__ __half2 g_hws2[NMAX * 32];  // fp16 dinv[src]-scaled conv output (row=32 half2)
__device__ float g_pre[NMAX * DMAX];   // pre-BN aggregated values (fp32)
__device__ float g_h[NMAX * DMAX];     // hidden state between layers
__device__ float g_dinv[NMAX];
__device__ int   g_cnt[NMAX];
__device__ int   g_incl[NMAX];
__device__ int   g_rowptr[NMAX + 1];
__device__ int   g_wpos[NMAX];
__device__ int   g_srcs[EMAX];
__device__ int   g_part[128];
__device__ float g_bnsum[DMAX], g_bnsumsq[DMAX];
__device__ float g_bnscale[DMAX], g_bnshift[DMAX];
__device__ int   g_gcnt[GMAX];
__device__ int   g_goff[GMAX];
__device__ float g_z[GMAX * 3 * DMAX];

// ---------------- helpers ----------------
__device__ __forceinline__ float gelu_exact(float x) {
    return 0.5f * x * (1.0f + erff(x * 0.70710678118654752f));
}

typedef unsigned long long ull;

__device__ __forceinline__ ull pack2(float lo, float hi) {
    ull r;
    asm("mov.b64 %0, {%1, %2};" : "=l"(r) : "f"(lo), "f"(hi));
    return r;
}
__device__ __forceinline__ void unpack2(ull v, float& lo, float& hi) {
    asm("mov.b64 {%0, %1}, %2;" : "=f"(lo), "=f"(hi) : "l"(v));
}
__device__ __forceinline__ void ffma2(ull& d, ull a, ull b) {
    asm("fma.rn.f32x2 %0, %1, %2, %0;" : "+l"(d) : "l"(a), "l"(b));
}

// ---------------- zero kernels ----------------
__global__ void zero_int(int* p, int n) {
    int i = blockIdx.x * blockDim.x + threadIdx.x;
    if (i < n) p[i] = 0;
}
__global__ void zero_bnsums() {
    int t = threadIdx.x;
    if (t < DMAX) { g_bnsum[t] = 0.f; g_bnsumsq[t] = 0.f; }
}

// ---------------- degree / dinv ----------------
__global__ void hist_edges(const int* __restrict__ ei, int E) {
    int e = blockIdx.x * blockDim.x + threadIdx.x;
    if (e < E) atomicAdd(&g_cnt[ei[E + e]], 1);   // dst row
}
__global__ void dinv_kernel(int n) {
    int i = blockIdx.x * blockDim.x + threadIdx.x;
    if (i < n) g_dinv[i] = rsqrtf((float)(g_cnt[i] + 1));  // +1 self-loop
}

// ---------------- CSR build: scan + place ----------------
__global__ void scan_blocks(int n) {
    __shared__ int sh[1024];
    int t = threadIdx.x;
    int i = blockIdx.x * 1024 + t;
    int v = (i < n) ? g_cnt[i] : 0;
    sh[t] = v;
    __syncthreads();
    for (int o = 1; o < 1024; o <<= 1) {
        int u = (t >= o) ? sh[t - o] : 0;
        __syncthreads();
        sh[t] += u;
        __syncthreads();
    }
    if (i < n) g_incl[i] = sh[t];
    if (t == 1023) g_part[blockIdx.x] = sh[1023];
}
__global__ void scan_partials(int nb) {
    __shared__ int sh[128];
    int t = threadIdx.x;
    int v = (t < nb) ? g_part[t] : 0;
    sh[t] = v;
    __syncthreads();
    for (int o = 1; o < 128; o <<= 1) {
        int u = (t >= o) ? sh[t - o] : 0;
        __syncthreads();
        sh[t] += u;
        __syncthreads();
    }
    g_part[t] = sh[t] - v;   // exclusive
}
__global__ void scan_finish(int n) {
    int i = blockIdx.x * 1024 + threadIdx.x;
    if (i < n) {
        int off = g_part[i >> 10];
        int incl = g_incl[i] + off;
        int rp = incl - g_cnt[i];
        g_rowptr[i] = rp;
        g_wpos[i]   = rp;
        if (i == n - 1) g_rowptr[n] = incl;
    }
}
__global__ void place_edges(const int* __restrict__ ei, int E) {
    int e = blockIdx.x * blockDim.x + threadIdx.x;
    if (e < E) {
        int s = ei[e], d = ei[E + e];
        int pos = atomicAdd(&g_wpos[d], 1);
        g_srcs[pos] = s;
    }
}

// ---------------- graph histogram + scan ----------------
__global__ void hist_batch(const int* __restrict__ batch, int n) {
    int i = blockIdx.x * blockDim.x + threadIdx.x;
    if (i < n) atomicAdd(&g_gcnt[batch[i]], 1);
}
__global__ void scan_goff() {
    __shared__ int sh[GMAX];
    int t = threadIdx.x;
    sh[t] = g_gcnt[t];
    __syncthreads();
    for (int o = 1; o < GMAX; o <<= 1) {
        int u = (t >= o) ? sh[t - o] : 0;
        __syncthreads();
        sh[t] += u;
        __syncthreads();
    }
    g_goff[t] = sh[t] - g_gcnt[t];   // exclusive
}

// ---------------- GEMM: hws2[n,c] = fp16( dinv[n] * sum_k H[n,k] W[k,c] ) ------
__global__ __launch_bounds__(256) void gemm_scaled(const float* __restrict__ H,
                                                   const float* __restrict__ W,
                                                   int n) {
    __shared__ float Ws[64 * 64];      // [k][c]
    __shared__ float Hs[64][65];       // padded
    int t = threadIdx.x;
    for (int i = t; i < 1024; i += 256)
        ((float4*)Ws)[i] = ((const float4*)W)[i];
    int row0 = blockIdx.x * 64;
    for (int i = t; i < 1024; i += 256) {
        int r = i >> 4, q = i & 15;
        int row = row0 + r;
        float4 v = (row < n) ? __ldg(&((const float4*)H)[row * 16 + q])
                             : make_float4(0.f, 0.f, 0.f, 0.f);
        Hs[r][q * 4 + 0] = v.x;
        Hs[r][q * 4 + 1] = v.y;
        Hs[r][q * 4 + 2] = v.z;
        Hs[r][q * 4 + 3] = v.w;
    }
    __syncthreads();
    int cq = (t & 15) * 4;
    int rb = (t >> 4) * 4;
    ull acc[4][2];
#pragma unroll
    for (int i = 0; i < 4; i++) { acc[i][0] = 0ull; acc[i][1] = 0ull; }
#pragma unroll 8
    for (int k = 0; k < 64; k++) {
        ull w01 = *(const ull*)&Ws[k * 64 + cq];
        ull w23 = *(const ull*)&Ws[k * 64 + cq + 2];
        ull h0 = pack2(Hs[rb + 0][k], Hs[rb + 0][k]);
        ull h1 = pack2(Hs[rb + 1][k], Hs[rb + 1][k]);
        ull h2 = pack2(Hs[rb + 2][k], Hs[rb + 2][k]);
        ull h3 = pack2(Hs[rb + 3][k], Hs[rb + 3][k]);
        ffma2(acc[0][0], h0, w01); ffma2(acc[0][1], h0, w23);
        ffma2(acc[1][0], h1, w01); ffma2(acc[1][1], h1, w23);
        ffma2(acc[2][0], h2, w01); ffma2(acc[2][1], h2, w23);
        ffma2(acc[3][0], h3, w01); ffma2(acc[3][1], h3, w23);
    }
#pragma unroll
    for (int i = 0; i < 4; i++) {
        int row = row0 + rb + i;
        if (row < n) {
            float di = g_dinv[row];
            float a0, a1, a2, a3;
            unpack2(acc[i][0], a0, a1);
            unpack2(acc[i][1], a2, a3);
            __half2 p01 = __floats2half2_rn(a0 * di, a1 * di);
            __half2 p23 = __floats2half2_rn(a2 * di, a3 * di);
            uint2 st;
            st.x = *(unsigned int*)&p01;
            st.y = *(unsigned int*)&p23;
            ((uint2*)g_hws2)[row * 16 + (cq >> 2)] = st;
        }
    }
}

// ---------------- CSR aggregate + self-loop + dinv scale + convB + BN partials --
__global__ __launch_bounds__(512) void aggregate(const float* __restrict__ convB,
                                                 int n) {
    __shared__ float bs[64], bs2[64];
    int t = threadIdx.x;
    if (t < 64) { bs[t] = 0.f; bs2[t] = 0.f; }
    __syncthreads();
    int r = (blockIdx.x * blockDim.x + t) >> 5;
    int lane = t & 31;
    if (r < n) {
        float2 a = __half22float2(g_hws2[r * 32 + lane]);   // self-loop term
        int p0 = g_rowptr[r], p1 = g_rowptr[r + 1];
#pragma unroll 4
        for (int p = p0; p < p1; p++) {
            int s = g_srcs[p];
            float2 f = __half22float2(g_hws2[s * 32 + lane]);
            a.x += f.x;
            a.y += f.y;
        }
        float di = g_dinv[r];
        float pre0 = fmaf(di, a.x, convB[2 * lane]);
        float pre1 = fmaf(di, a.y, convB[2 * lane + 1]);
        float2 st; st.x = pre0; st.y = pre1;
        ((float2*)g_pre)[r * 32 + lane] = st;
        atomicAdd(&bs[2 * lane], pre0);
        atomicAdd(&bs[2 * lane + 1], pre1);
        atomicAdd(&bs2[2 * lane], pre0 * pre0);
        atomicAdd(&bs2[2 * lane + 1], pre1 * pre1);
    }
    __syncthreads();
    if (t < 64) {
        atomicAdd(&g_bnsum[t], bs[t]);
        atomicAdd(&g_bnsumsq[t], bs2[t]);
    }
}

__global__ void bn_final(const float* __restrict__ bng, const float* __restrict__ bnb,
                         float invN) {
    int d = threadIdx.x;
    float mu  = g_bnsum[d] * invN;
    float var = g_bnsumsq[d] * invN - mu * mu;
    float rstd = rsqrtf(var + 1e-5f);
    float sc = rstd * bng[d];
    g_bnscale[d] = sc;
    g_bnshift[d] = bnb[d] - mu * sc;
}

// ---------------- BN apply + residual + LayerNorm + GELU ----------------
__global__ void norm_act(const float* __restrict__ lng, const float* __restrict__ lnb,
                         const float* __restrict__ xin,   // residual (null for layer 0)
                         float* __restrict__ hout, int n) {
    int r = (blockIdx.x * blockDim.x + threadIdx.x) >> 5;
    int lane = threadIdx.x & 31;
    if (r >= n) return;
    int i0 = r * 64 + lane, i1 = i0 + 32;
    float v0 = g_pre[i0] * g_bnscale[lane]      + g_bnshift[lane];
    float v1 = g_pre[i1] * g_bnscale[lane + 32] + g_bnshift[lane + 32];
    if (xin) { v0 += xin[i0]; v1 += xin[i1]; }
    float s = v0 + v1;
#pragma unroll
    for (int o = 16; o; o >>= 1) s += __shfl_xor_sync(0xffffffffu, s, o);
    float mu = s * (1.0f / 64.0f);
    float d0 = v0 - mu, d1 = v1 - mu;
    float vv = d0 * d0 + d1 * d1;
#pragma unroll
    for (int o = 16; o; o >>= 1) vv += __shfl_xor_sync(0xffffffffu, vv, o);
    float rstd = rsqrtf(vv * (1.0f / 64.0f) + 1e-5f);
    float y0 = d0 * rstd * lng[lane]      + lnb[lane];
    float y1 = d1 * rstd * lng[lane + 32] + lnb[lane + 32];
    hout[i0] = gelu_exact(y0);
    hout[i1] = gelu_exact(y1);
}

// ---------------- pooling (batch sorted -> contiguous segments) ----------------
__global__ void pool_graphs() {
    int g = blockIdx.x;
    int start = g_goff[g], cnt = g_gcnt[g];
    int d = threadIdx.x & 63, lane = threadIdx.x >> 6;
    float s = 0.f, m = -FLT_MAX;
    for (int r = start + lane; r < start + cnt; r += 4) {
        float v = g_h[r * 64 + d];
        s += v; m = fmaxf(m, v);
    }
    __shared__ float shs[4][64], shm[4][64];
    shs[lane][d] = s; shm[lane][d] = m;
    __syncthreads();
    if (lane == 0) {
        s = shs[0][d] + shs[1][d] + shs[2][d] + shs[3][d];
        m = fmaxf(fmaxf(shm[0][d], shm[1][d]), fmaxf(shm[2][d], shm[3][d]));
        float mean = (cnt > 0) ? s / (float)cnt : 0.f;
        if (cnt == 0) { m = 0.f; s = 0.f; }
        g_z[g * 192 + d]        = mean;
        g_z[g * 192 + 64 + d]   = m;
        g_z[g * 192 + 128 + d]  = s;
    }
}

// ---------------- fused MLP head: 192 -> 128 -> 64 -> 1 ----------------
__global__ void mlp_head(const float* __restrict__ W1, const float* __restrict__ b1,
                         const float* __restrict__ l1g, const float* __restrict__ l1b,
                         const float* __restrict__ W2, const float* __restrict__ b2,
                         const float* __restrict__ l2g, const float* __restrict__ l2b,
                         const float* __restrict__ W3, const float* __restrict__ b3,
                         float* __restrict__ out) {
    int g = blockIdx.x, t = threadIdx.x;   // 128 threads
    __shared__ float zs[192];
    __shared__ float s2[128];
    __shared__ float red[128];
    for (int i = t; i < 192; i += 128) zs[i] = g_z[g * 192 + i];
    __syncthreads();
    float acc = b1[t];
#pragma unroll 4
    for (int k = 0; k < 192; k++) acc = fmaf(zs[k], W1[k * 128 + t], acc);
    red[t] = acc; __syncthreads();
    for (int o = 64; o > 0; o >>= 1) { if (t < o) red[t] += red[t + o]; __syncthreads(); }
    float mu = red[0] * (1.0f / 128.0f); __syncthreads();
    float dv = acc - mu;
    red[t] = dv * dv; __syncthreads();
    for (int o = 64; o > 0; o >>= 1) { if (t < o) red[t] += red[t + o]; __syncthreads(); }
    float rstd = rsqrtf(red[0] * (1.0f / 128.0f) + 1e-5f); __syncthreads();
    float y = dv * rstd * l1g[t] + l1b[t];
    s2[t] = gelu_exact(y);
    __syncthreads();
    float acc2 = 0.f;
    if (t < 64) {
        acc2 = b2[t];
#pragma unroll 4
        for (int k = 0; k < 128; k++) acc2 = fmaf(s2[k], W2[k * 64 + t], acc2);
    }
    red[t] = (t < 64) ? acc2 : 0.f; __syncthreads();
    for (int o = 64; o > 0; o >>= 1) { if (t < o) red[t] += red[t + o]; __syncthreads(); }
    float mu2 = red[0] * (1.0f / 64.0f); __syncthreads();
    float dv2 = acc2 - mu2;
    red[t] = (t < 64) ? dv2 * dv2 : 0.f; __syncthreads();
    for (int o = 64; o > 0; o >>= 1) { if (t < o) red[t] += red[t + o]; __syncthreads(); }
    float rstd2 = rsqrtf(red[0] * (1.0f / 64.0f) + 1e-5f); __syncthreads();
    float y2 = 0.f;
    if (t < 64) y2 = gelu_exact(dv2 * rstd2 * l2g[t] + l2b[t]);
    red[t] = (t < 64) ? y2 * W3[t] : 0.f; __syncthreads();
    for (int o = 64; o > 0; o >>= 1) { if (t < o) red[t] += red[t + o]; __syncthreads(); }
    if (t == 0) out[g] = red[0] + b3[0];
}

// ---------------- host ----------------
extern "C" void kernel_launch(void* const* d_in, const int* in_sizes, int n_in,
                              void* d_out, int out_size) {
    const float* x     = (const float*)d_in[0];
    const int*   ei    = (const int*)d_in[1];
    const int*   batch = (const int*)d_in[2];
    const float* convW = (const float*)d_in[3];
    const float* convB = (const float*)d_in[4];
    const float* bn_g  = (const float*)d_in[5];
    const float* bn_b  = (const float*)d_in[6];
    const float* ln_g  = (const float*)d_in[7];
    const float* ln_b  = (const float*)d_in[8];
    const float* W1    = (const float*)d_in[9];
    const float* b1    = (const float*)d_in[10];
    const float* l1g   = (const float*)d_in[11];
    const float* l1b   = (const float*)d_in[12];
    const float* W2    = (const float*)d_in[13];
    const float* b2    = (const float*)d_in[14];
    const float* l2g   = (const float*)d_in[15];
    const float* l2b   = (const float*)d_in[16];
    const float* W3    = (const float*)d_in[17];
    const float* b3    = (const float*)d_in[18];
    float* out = (float*)d_out;

    const int N = in_sizes[0] / 64;
    const int E = in_sizes[1] / 2;
    const int G = out_size;          // 512
    const int L = in_sizes[3] / (64 * 64);

    int* p_cnt; int* p_gcnt; float* p_h;
    cudaGetSymbolAddress((void**)&p_cnt,  g_cnt);
    cudaGetSymbolAddress((void**)&p_gcnt, g_gcnt);
    cudaGetSymbolAddress((void**)&p_h,    g_h);

    const int TB = 256;
    // degrees -> dinv, then CSR
    zero_int<<<(N + TB - 1) / TB, TB>>>(p_cnt, N);
    hist_edges<<<(E + TB - 1) / TB, TB>>>(ei, E);
    dinv_kernel<<<(N + TB - 1) / TB, TB>>>(N);
    int nb = (N + 1023) / 1024;
    scan_blocks<<<nb, 1024>>>(N);
    scan_partials<<<1, 128>>>(nb);
    scan_finish<<<nb, 1024>>>(N);
    place_edges<<<(E + TB - 1) / TB, TB>>>(ei, E);

    // graph segment offsets
    zero_int<<<(G + TB - 1) / TB, TB>>>(p_gcnt, G);
    hist_batch<<<(N + TB - 1) / TB, TB>>>(batch, N);
    scan_goff<<<1, G>>>();

    const float* h_cur = x;
    for (int i = 0; i < L; i++) {
        zero_bnsums<<<1, 64>>>();
        gemm_scaled<<<(N + 63) / 64, 256>>>(h_cur, convW + i * 64 * 64, N);
        aggregate<<<(N * 32 + 511) / 512, 512>>>(convB + i * 64, N);
        bn_final<<<1, 64>>>(bn_g + i * 64, bn_b + i * 64, 1.0f / (float)N);
        const float* xin = (i == 0) ? (const float*)nullptr : (const float*)p_h;
        norm_act<<<(N * 32 + TB - 1) / TB, TB>>>(ln_g + i * 64, ln_b + i * 64,
                                                 xin, p_h, N);
        h_cur = p_h;
    }

    pool_graphs<<<G, 256>>>();
    mlp_head<<<G, 128>>>(W1, b1, l1g, l1b, W2, b2, l2g, l2b, W3, b3, out);
}

// round 5
// speedup vs baseline: 2.1775x; 1.0878x over previous
#include <cuda_runtime.h>
#include <cuda_fp16.h>
#include <float.h>
#include <math.h>

#define DMAX 64
#define NMAX 100000
#define EMAX 1600000
#define GMAX 512
#define LMAX 3

// ---------------- scratch (no allocations allowed) ----------------
__device__ __half2 g_hws2[NMAX * 32];  // fp16 dinv[src]-scaled conv output
__device__ float g_pre[NMAX * DMAX];   // pre-BN aggregated values (fp32)
__device__ float g_h[NMAX * DMAX];     // hidden state between layers
__device__ float g_dinv[NMAX];
__device__ int   g_cnt[NMAX];
__device__ int   g_incl[NMAX];
__device__ int   g_rowptr[NMAX + 1];
__device__ int   g_wpos[NMAX];
__device__ int   g_srcs[EMAX];
__device__ int   g_part[128];
__device__ float g_bnsum[LMAX * DMAX], g_bnsumsq[LMAX * DMAX];
__device__ int   g_gcnt[GMAX];
__device__ int   g_goff[GMAX];

// ---------------- helpers ----------------
__device__ __forceinline__ float gelu_exact(float x) {
    return 0.5f * x * (1.0f + erff(x * 0.70710678118654752f));
}

typedef unsigned long long ull;

__device__ __forceinline__ ull pack2(float lo, float hi) {
    ull r;
    asm("mov.b64 %0, {%1, %2};" : "=l"(r) : "f"(lo), "f"(hi));
    return r;
}
__device__ __forceinline__ void unpack2(ull v, float& lo, float& hi) {
    asm("mov.b64 {%0, %1}, %2;" : "=f"(lo), "=f"(hi) : "l"(v));
}
__device__ __forceinline__ void ffma2(ull& d, ull a, ull b) {
    asm("fma.rn.f32x2 %0, %1, %2, %0;" : "+l"(d) : "l"(a), "l"(b));
}

// ---------------- setup: zero everything that gets accumulated ----------------
__global__ void setup_zero(int n, int g) {
    int i = blockIdx.x * blockDim.x + threadIdx.x;
    int stride = gridDim.x * blockDim.x;
    for (int k = i; k < n; k += stride) g_cnt[k] = 0;
    if (i < g) g_gcnt[i] = 0;
    if (i < LMAX * DMAX) { g_bnsum[i] = 0.f; g_bnsumsq[i] = 0.f; }
}

// ---------------- combined histogram: edge degrees + batch counts ------------
__global__ void hist_both(const int* __restrict__ ei, const int* __restrict__ batch,
                          int E, int n) {
    int i = blockIdx.x * blockDim.x + threadIdx.x;
    if (i < E) {
        atomicAdd(&g_cnt[ei[E + i]], 1);   // dst row degree
    } else if (i - E < n) {
        atomicAdd(&g_gcnt[batch[i - E]], 1);
    }
}

// ---------------- CSR build: scan + place ----------------
__global__ void scan_blocks(int n) {
    __shared__ int sh[1024];
    int t = threadIdx.x;
    int i = blockIdx.x * 1024 + t;
    int v = (i < n) ? g_cnt[i] : 0;
    sh[t] = v;
    __syncthreads();
    for (int o = 1; o < 1024; o <<= 1) {
        int u = (t >= o) ? sh[t - o] : 0;
        __syncthreads();
        sh[t] += u;
        __syncthreads();
    }
    if (i < n) g_incl[i] = sh[t];
    if (t == 1023) g_part[blockIdx.x] = sh[1023];
}
// block 0: exclusive-scan partials (128);  block 1: exclusive-scan graph counts (512)
__global__ void scan_mid(int nb) {
    if (blockIdx.x == 0) {
        __shared__ int sh[128];
        int t = threadIdx.x;
        if (t < 128) {
            int v = (t < nb) ? g_part[t] : 0;
            sh[t] = v;
            __syncthreads();
            for (int o = 1; o < 128; o <<= 1) {
                int u = (t >= o) ? sh[t - o] : 0;
                __syncthreads();
                sh[t] += u;
                __syncthreads();
            }
            g_part[t] = sh[t] - v;   // exclusive
        }
    } else {
        __shared__ int sh[GMAX];
        int t = threadIdx.x;
        int v = g_gcnt[t];
        sh[t] = v;
        __syncthreads();
        for (int o = 1; o < GMAX; o <<= 1) {
            int u = (t >= o) ? sh[t - o] : 0;
            __syncthreads();
            sh[t] += u;
            __syncthreads();
        }
        g_goff[t] = sh[t] - v;   // exclusive
    }
}
__global__ void scan_finish(int n) {
    int i = blockIdx.x * 1024 + threadIdx.x;
    if (i < n) {
        int c = g_cnt[i];
        int off = g_part[i >> 10];
        int incl = g_incl[i] + off;
        int rp = incl - c;
        g_rowptr[i] = rp;
        g_wpos[i]   = rp;
        g_dinv[i]   = rsqrtf((float)(c + 1));   // +1 self-loop
        if (i == n - 1) g_rowptr[n] = incl;
    }
}
__global__ void place_edges(const int* __restrict__ ei, int E) {
    int e = blockIdx.x * blockDim.x + threadIdx.x;
    if (e < E) {
        int s = ei[e], d = ei[E + e];
        int pos = atomicAdd(&g_wpos[d], 1);
        g_srcs[pos] = s;
    }
}

// ---------------- fused layer: [BN+res+LN+GELU transform] + GEMM --------------
// If pre == nullptr: load xsrc rows raw (layer 0).
// Else: h_row = gelu(LN(bn(pre_row) [+ residual from hio])) ; store to hio + smem.
// Then: hws2[row,:] = fp16( dinv[row] * h_row @ W )
__global__ __launch_bounds__(256) void fused_layer(
    const float* __restrict__ xsrc,
    const float* __restrict__ pre,
    const float* __restrict__ bnsum, const float* __restrict__ bnsumsq,
    const float* __restrict__ bng, const float* __restrict__ bnb,
    const float* __restrict__ lng, const float* __restrict__ lnb,
    float* __restrict__ hio, int useRes,
    const float* __restrict__ W, float invN, int n) {
    __shared__ float Ws[64 * 64];      // [k][c]
    __shared__ float Hs[64][65];       // padded
    int t = threadIdx.x;
    for (int i = t; i < 1024; i += 256)
        ((float4*)Ws)[i] = ((const float4*)W)[i];
    int row0 = blockIdx.x * 64;

    if (pre == nullptr) {
        for (int i = t; i < 1024; i += 256) {
            int r = i >> 4, q = i & 15;
            int row = row0 + r;
            float4 v = (row < n) ? __ldg(&((const float4*)xsrc)[row * 16 + q])
                                 : make_float4(0.f, 0.f, 0.f, 0.f);
            Hs[r][q * 4 + 0] = v.x;
            Hs[r][q * 4 + 1] = v.y;
            Hs[r][q * 4 + 2] = v.z;
            Hs[r][q * 4 + 3] = v.w;
        }
    } else {
        int w = t >> 5, lane = t & 31;
        // per-feature BN scale/shift (features lane and lane+32)
        float mu0 = bnsum[lane] * invN;
        float var0 = bnsumsq[lane] * invN - mu0 * mu0;
        float sc0 = rsqrtf(var0 + 1e-5f) * bng[lane];
        float sh0 = bnb[lane] - mu0 * sc0;
        float mu1 = bnsum[lane + 32] * invN;
        float var1 = bnsumsq[lane + 32] * invN - mu1 * mu1;
        float sc1 = rsqrtf(var1 + 1e-5f) * bng[lane + 32];
        float sh1 = bnb[lane + 32] - mu1 * sc1;
        float lg0 = lng[lane], lb0 = lnb[lane];
        float lg1 = lng[lane + 32], lb1 = lnb[lane + 32];
#pragma unroll
        for (int rr = 0; rr < 8; rr++) {
            int r = w * 8 + rr;
            int row = row0 + r;
            if (row < n) {
                int i0 = row * 64 + lane, i1 = i0 + 32;
                float v0 = pre[i0] * sc0 + sh0;
                float v1 = pre[i1] * sc1 + sh1;
                if (useRes) { v0 += hio[i0]; v1 += hio[i1]; }
                float s = v0 + v1;
#pragma unroll
                for (int o = 16; o; o >>= 1) s += __shfl_xor_sync(0xffffffffu, s, o);
                float mu = s * (1.0f / 64.0f);
                float d0 = v0 - mu, d1 = v1 - mu;
                float vv = d0 * d0 + d1 * d1;
#pragma unroll
                for (int o = 16; o; o >>= 1) vv += __shfl_xor_sync(0xffffffffu, vv, o);
                float rstd = rsqrtf(vv * (1.0f / 64.0f) + 1e-5f);
                float y0 = gelu_exact(d0 * rstd * lg0 + lb0);
                float y1 = gelu_exact(d1 * rstd * lg1 + lb1);
                Hs[r][lane] = y0;
                Hs[r][lane + 32] = y1;
                hio[i0] = y0;
                hio[i1] = y1;
            } else {
                Hs[r][lane] = 0.f;
                Hs[r][lane + 32] = 0.f;
            }
        }
    }
    __syncthreads();

    int cq = (t & 15) * 4;
    int rb = (t >> 4) * 4;
    ull acc[4][2];
#pragma unroll
    for (int i = 0; i < 4; i++) { acc[i][0] = 0ull; acc[i][1] = 0ull; }
#pragma unroll 8
    for (int k = 0; k < 64; k++) {
        ull w01 = *(const ull*)&Ws[k * 64 + cq];
        ull w23 = *(const ull*)&Ws[k * 64 + cq + 2];
        ull h0 = pack2(Hs[rb + 0][k], Hs[rb + 0][k]);
        ull h1 = pack2(Hs[rb + 1][k], Hs[rb + 1][k]);
        ull h2 = pack2(Hs[rb + 2][k], Hs[rb + 2][k]);
        ull h3 = pack2(Hs[rb + 3][k], Hs[rb + 3][k]);
        ffma2(acc[0][0], h0, w01); ffma2(acc[0][1], h0, w23);
        ffma2(acc[1][0], h1, w01); ffma2(acc[1][1], h1, w23);
        ffma2(acc[2][0], h2, w01); ffma2(acc[2][1], h2, w23);
        ffma2(acc[3][0], h3, w01); ffma2(acc[3][1], h3, w23);
    }
#pragma unroll
    for (int i = 0; i < 4; i++) {
        int row = row0 + rb + i;
        if (row < n) {
            float di = g_dinv[row];
            float a0, a1, a2, a3;
            unpack2(acc[i][0], a0, a1);
            unpack2(acc[i][1], a2, a3);
            __half2 p01 = __floats2half2_rn(a0 * di, a1 * di);
            __half2 p23 = __floats2half2_rn(a2 * di, a3 * di);
            uint2 st;
            st.x = *(unsigned int*)&p01;
            st.y = *(unsigned int*)&p23;
            ((uint2*)g_hws2)[row * 16 + (cq >> 2)] = st;
        }
    }
}

// ---------------- CSR aggregate + self-loop + dinv scale + convB + BN partials --
__global__ __launch_bounds__(512) void aggregate(const float* __restrict__ convB,
                                                 float* __restrict__ bnsum,
                                                 float* __restrict__ bnsumsq,
                                                 int n) {
    __shared__ float bs[64], bs2[64];
    int t = threadIdx.x;
    if (t < 64) { bs[t] = 0.f; bs2[t] = 0.f; }
    __syncthreads();
    int r = (blockIdx.x * blockDim.x + t) >> 5;
    int lane = t & 31;
    if (r < n) {
        float2 a = __half22float2(g_hws2[r * 32 + lane]);   // self-loop term
        int p0 = g_rowptr[r], p1 = g_rowptr[r + 1];
#pragma unroll 4
        for (int p = p0; p < p1; p++) {
            int s = g_srcs[p];
            float2 f = __half22float2(g_hws2[s * 32 + lane]);
            a.x += f.x;
            a.y += f.y;
        }
        float di = g_dinv[r];
        float pre0 = fmaf(di, a.x, convB[2 * lane]);
        float pre1 = fmaf(di, a.y, convB[2 * lane + 1]);
        float2 st; st.x = pre0; st.y = pre1;
        ((float2*)g_pre)[r * 32 + lane] = st;
        atomicAdd(&bs[2 * lane], pre0);
        atomicAdd(&bs[2 * lane + 1], pre1);
        atomicAdd(&bs2[2 * lane], pre0 * pre0);
        atomicAdd(&bs2[2 * lane + 1], pre1 * pre1);
    }
    __syncthreads();
    if (t < 64) {
        atomicAdd(&bnsum[t], bs[t]);
        atomicAdd(&bnsumsq[t], bs2[t]);
    }
}

// ---------------- final transform (no GEMM after): BN+res+LN+GELU -> g_h ------
__global__ void final_norm(const float* __restrict__ bnsum,
                           const float* __restrict__ bnsumsq,
                           const float* __restrict__ bng, const float* __restrict__ bnb,
                           const float* __restrict__ lng, const float* __restrict__ lnb,
                           float* __restrict__ hio, float invN, int n) {
    int r = (blockIdx.x * blockDim.x + threadIdx.x) >> 5;
    int lane = threadIdx.x & 31;
    if (r >= n) return;
    float mu0 = bnsum[lane] * invN;
    float var0 = bnsumsq[lane] * invN - mu0 * mu0;
    float sc0 = rsqrtf(var0 + 1e-5f) * bng[lane];
    float sh0 = bnb[lane] - mu0 * sc0;
    float mu1 = bnsum[lane + 32] * invN;
    float var1 = bnsumsq[lane + 32] * invN - mu1 * mu1;
    float sc1 = rsqrtf(var1 + 1e-5f) * bng[lane + 32];
    float sh1 = bnb[lane + 32] - mu1 * sc1;
    int i0 = r * 64 + lane, i1 = i0 + 32;
    float v0 = g_pre[i0] * sc0 + sh0 + hio[i0];
    float v1 = g_pre[i1] * sc1 + sh1 + hio[i1];
    float s = v0 + v1;
#pragma unroll
    for (int o = 16; o; o >>= 1) s += __shfl_xor_sync(0xffffffffu, s, o);
    float mu = s * (1.0f / 64.0f);
    float d0 = v0 - mu, d1 = v1 - mu;
    float vv = d0 * d0 + d1 * d1;
#pragma unroll
    for (int o = 16; o; o >>= 1) vv += __shfl_xor_sync(0xffffffffu, vv, o);
    float rstd = rsqrtf(vv * (1.0f / 64.0f) + 1e-5f);
    hio[i0] = gelu_exact(d0 * rstd * lng[lane] + lnb[lane]);
    hio[i1] = gelu_exact(d1 * rstd * lng[lane + 32] + lnb[lane + 32]);
}

// ---------------- fused pool + MLP head per graph ----------------
__global__ __launch_bounds__(256) void pool_mlp(
    const float* __restrict__ W1, const float* __restrict__ b1,
    const float* __restrict__ l1g, const float* __restrict__ l1b,
    const float* __restrict__ W2, const float* __restrict__ b2,
    const float* __restrict__ l2g, const float* __restrict__ l2b,
    const float* __restrict__ W3, const float* __restrict__ b3,
    float* __restrict__ out) {
    int g = blockIdx.x, t = threadIdx.x;   // 256 threads
    __shared__ float zs[192];
    __shared__ float shs[4][64], shm[4][64];
    __shared__ float s2[128];
    __shared__ float red[128];

    // ---- pool phase (all 256 threads) ----
    int start = g_goff[g], cnt = g_gcnt[g];
    int d = t & 63, lane = t >> 6;
    float s = 0.f, m = -FLT_MAX;
    for (int r = start + lane; r < start + cnt; r += 4) {
        float v = g_h[r * 64 + d];
        s += v; m = fmaxf(m, v);
    }
    shs[lane][d] = s; shm[lane][d] = m;
    __syncthreads();
    if (lane == 0) {
        s = shs[0][d] + shs[1][d] + shs[2][d] + shs[3][d];
        m = fmaxf(fmaxf(shm[0][d], shm[1][d]), fmaxf(shm[2][d], shm[3][d]));
        float mean = (cnt > 0) ? s / (float)cnt : 0.f;
        if (cnt == 0) { m = 0.f; s = 0.f; }
        zs[d] = mean;
        zs[64 + d] = m;
        zs[128 + d] = s;
    }
    __syncthreads();

    // ---- MLP phase (first 128 threads) ----
    if (t < 128) {
        float acc = b1[t];
#pragma unroll 4
        for (int k = 0; k < 192; k++) acc = fmaf(zs[k], W1[k * 128 + t], acc);
        red[t] = acc;
    }
    __syncthreads();
    if (t < 128) {
        for (int o = 64; o > 0; o >>= 1) {
            if (t < o) red[t] += red[t + o];
            __syncwarp(0xffffffffu);
            if (o > 32) __syncthreads();
        }
    }
    __syncthreads();
    float mu = red[0] * (1.0f / 128.0f);
    __syncthreads();
    if (t < 128) {
        float acc = b1[t];
#pragma unroll 4
        for (int k = 0; k < 192; k++) acc = fmaf(zs[k], W1[k * 128 + t], acc);
        float dv = acc - mu;
        red[t] = dv * dv;
        s2[t] = dv;
    }
    __syncthreads();
    if (t < 128) {
        for (int o = 64; o > 0; o >>= 1) {
            if (t < o) red[t] += red[t + o];
            __syncwarp(0xffffffffu);
            if (o > 32) __syncthreads();
        }
    }
    __syncthreads();
    float rstd = rsqrtf(red[0] * (1.0f / 128.0f) + 1e-5f);
    __syncthreads();
    if (t < 128) {
        s2[t] = gelu_exact(s2[t] * rstd * l1g[t] + l1b[t]);
    }
    __syncthreads();
    // layer 2: 128 -> 64
    float acc2 = 0.f;
    if (t < 64) {
        acc2 = b2[t];
#pragma unroll 4
        for (int k = 0; k < 128; k++) acc2 = fmaf(s2[k], W2[k * 64 + t], acc2);
    }
    if (t < 128) red[t] = (t < 64) ? acc2 : 0.f;
    __syncthreads();
    if (t < 128) {
        for (int o = 64; o > 0; o >>= 1) {
            if (t < o) red[t] += red[t + o];
            __syncwarp(0xffffffffu);
            if (o > 32) __syncthreads();
        }
    }
    __syncthreads();
    float mu2 = red[0] * (1.0f / 64.0f);
    __syncthreads();
    float dv2 = acc2 - mu2;
    if (t < 128) red[t] = (t < 64) ? dv2 * dv2 : 0.f;
    __syncthreads();
    if (t < 128) {
        for (int o = 64; o > 0; o >>= 1) {
            if (t < o) red[t] += red[t + o];
            __syncwarp(0xffffffffu);
            if (o > 32) __syncthreads();
        }
    }
    __syncthreads();
    float rstd2 = rsqrtf(red[0] * (1.0f / 64.0f) + 1e-5f);
    __syncthreads();
    float y2 = 0.f;
    if (t < 64) y2 = gelu_exact(dv2 * rstd2 * l2g[t] + l2b[t]);
    if (t < 128) red[t] = (t < 64) ? y2 * W3[t] : 0.f;
    __syncthreads();
    if (t < 128) {
        for (int o = 64; o > 0; o >>= 1) {
            if (t < o) red[t] += red[t + o];
            __syncwarp(0xffffffffu);
            if (o > 32) __syncthreads();
        }
    }
    __syncthreads();
    if (t == 0) out[g] = red[0] + b3[0];
}

// ---------------- host ----------------
extern "C" void kernel_launch(void* const* d_in, const int* in_sizes, int n_in,
                              void* d_out, int out_size) {
    const float* x     = (const float*)d_in[0];
    const int*   ei    = (const int*)d_in[1];
    const int*   batch = (const int*)d_in[2];
    const float* convW = (const float*)d_in[3];
    const float* convB = (const float*)d_in[4];
    const float* bn_g  = (const float*)d_in[5];
    const float* bn_b  = (const float*)d_in[6];
    const float* ln_g  = (const float*)d_in[7];
    const float* ln_b  = (const float*)d_in[8];
    const float* W1    = (const float*)d_in[9];
    const float* b1    = (const float*)d_in[10];
    const float* l1g   = (const float*)d_in[11];
    const float* l1b   = (const float*)d_in[12];
    const float* W2    = (const float*)d_in[13];
    const float* b2    = (const float*)d_in[14];
    const float* l2g   = (const float*)d_in[15];
    const float* l2b   = (const float*)d_in[16];
    const float* W3    = (const float*)d_in[17];
    const float* b3    = (const float*)d_in[18];
    float* out = (float*)d_out;

    const int N = in_sizes[0] / 64;
    const int E = in_sizes[1] / 2;
    const int G = out_size;          // 512
    const int L = in_sizes[3] / (64 * 64);
    const float invN = 1.0f / (float)N;

    float* p_h; float* p_pre; float* p_bnsum; float* p_bnsumsq;
    cudaGetSymbolAddress((void**)&p_h,       g_h);
    cudaGetSymbolAddress((void**)&p_pre,     g_pre);
    cudaGetSymbolAddress((void**)&p_bnsum,   g_bnsum);
    cudaGetSymbolAddress((void**)&p_bnsumsq, g_bnsumsq);

    const int TB = 256;
    // setup: zero + combined hist + CSR scan + place
    setup_zero<<<(N + TB - 1) / TB, TB>>>(N, G);
    hist_both<<<(E + N + TB - 1) / TB, TB>>>(ei, batch, E, N);
    int nb = (N + 1023) / 1024;
    scan_blocks<<<nb, 1024>>>(N);
    scan_mid<<<2, 512>>>(nb);
    scan_finish<<<nb, 1024>>>(N);
    place_edges<<<(E + TB - 1) / TB, TB>>>(ei, E);

    int fgrid = (N + 63) / 64;
    int agrid = (N * 32 + 511) / 512;

    // layer 0 gemm (raw x input)
    fused_layer<<<fgrid, 256>>>(x, nullptr, nullptr, nullptr, nullptr, nullptr,
                                nullptr, nullptr, p_h, 0, convW, invN, N);
    aggregate<<<agrid, 512>>>(convB, p_bnsum, p_bnsumsq, N);

    // layer 1: transform layer-0 output (no residual) + gemm W1
    fused_layer<<<fgrid, 256>>>(nullptr, p_pre, p_bnsum, p_bnsumsq,
                                bn_g, bn_b, ln_g, ln_b,
                                p_h, 0, convW + 64 * 64, invN, N);
    aggregate<<<agrid, 512>>>(convB + 64, p_bnsum + 64, p_bnsumsq + 64, N);

    // layer 2: transform layer-1 output (residual) + gemm W2
    fused_layer<<<fgrid, 256>>>(nullptr, p_pre, p_bnsum + 64, p_bnsumsq + 64,
                                bn_g + 64, bn_b + 64, ln_g + 64, ln_b + 64,
                                p_h, 1, convW + 2 * 64 * 64, invN, N);
    aggregate<<<agrid, 512>>>(convB + 2 * 64, p_bnsum + 2 * 64, p_bnsumsq + 2 * 64, N);

    // final transform (residual, no gemm)
    final_norm<<<(N * 32 + TB - 1) / TB, TB>>>(p_bnsum + 2 * 64, p_bnsumsq + 2 * 64,
                                               bn_g + 2 * 64, bn_b + 2 * 64,
                                               ln_g + 2 * 64, ln_b + 2 * 64,
                                               p_h, invN, N);

    pool_mlp<<<G, 256>>>(W1, b1, l1g, l1b, W2, b2, l2g, l2b, W3, b3, out);
}

// round 6
// speedup vs baseline: 2.3930x; 1.0990x over previous
#include <cuda_runtime.h>
#include <cuda_fp16.h>
#include <float.h>
#include <math.h>

#define DMAX 64
#define NMAX 100000
#define EMAX 1600000
#define GMAX 512
#define LMAX 3

// ---------------- scratch (no allocations allowed) ----------------
__device__ __align__(16) __half2 g_hws2[NMAX * 32];  // fp16 scaled conv output
__device__ float g_pre[NMAX * DMAX];   // pre-BN aggregated values (fp32)
__device__ float g_h[NMAX * DMAX];     // hidden state between layers
__device__ float g_dinv[NMAX];
__device__ int   g_cnt[NMAX];
__device__ int   g_incl[NMAX];
__device__ int   g_rowptr[NMAX + 1];
__device__ int   g_wpos[NMAX];
__device__ int   g_srcs[EMAX];
__device__ int   g_part[128];
__device__ float g_bnsum[LMAX * DMAX], g_bnsumsq[LMAX * DMAX];
__device__ int   g_gcnt[GMAX];
__device__ int   g_goff[GMAX];

// ---------------- helpers ----------------
__device__ __forceinline__ float gelu_exact(float x) {
    return 0.5f * x * (1.0f + erff(x * 0.70710678118654752f));
}

typedef unsigned long long ull;

__device__ __forceinline__ ull pack2(float lo, float hi) {
    ull r;
    asm("mov.b64 %0, {%1, %2};" : "=l"(r) : "f"(lo), "f"(hi));
    return r;
}
__device__ __forceinline__ void unpack2(ull v, float& lo, float& hi) {
    asm("mov.b64 {%0, %1}, %2;" : "=f"(lo), "=f"(hi) : "l"(v));
}
__device__ __forceinline__ void ffma2(ull& d, ull a, ull b) {
    asm("fma.rn.f32x2 %0, %1, %2, %0;" : "+l"(d) : "l"(a), "l"(b));
}

__device__ __forceinline__ void acc8(uint4 v, float* a) {
    float2 f;
    f = __half22float2(*(__half2*)&v.x); a[0] += f.x; a[1] += f.y;
    f = __half22float2(*(__half2*)&v.y); a[2] += f.x; a[3] += f.y;
    f = __half22float2(*(__half2*)&v.z); a[4] += f.x; a[5] += f.y;
    f = __half22float2(*(__half2*)&v.w); a[6] += f.x; a[7] += f.y;
}

// ---------------- setup: zero everything that gets accumulated ----------------
__global__ void setup_zero(int n, int g) {
    int i = blockIdx.x * blockDim.x + threadIdx.x;
    int stride = gridDim.x * blockDim.x;
    for (int k = i; k < n; k += stride) g_cnt[k] = 0;
    if (i < g) g_gcnt[i] = 0;
    if (i < LMAX * DMAX) { g_bnsum[i] = 0.f; g_bnsumsq[i] = 0.f; }
}

// ---------------- combined histogram: edge degrees + batch counts ------------
__global__ void hist_both(const int* __restrict__ ei, const int* __restrict__ batch,
                          int E, int n) {
    int i = blockIdx.x * blockDim.x + threadIdx.x;
    if (i < E) {
        atomicAdd(&g_cnt[ei[E + i]], 1);   // dst row degree
    } else if (i - E < n) {
        atomicAdd(&g_gcnt[batch[i - E]], 1);
    }
}

// ---------------- CSR build: scan + place ----------------
__global__ void scan_blocks(int n) {
    __shared__ int sh[1024];
    int t = threadIdx.x;
    int i = blockIdx.x * 1024 + t;
    int v = (i < n) ? g_cnt[i] : 0;
    sh[t] = v;
    __syncthreads();
    for (int o = 1; o < 1024; o <<= 1) {
        int u = (t >= o) ? sh[t - o] : 0;
        __syncthreads();
        sh[t] += u;
        __syncthreads();
    }
    if (i < n) g_incl[i] = sh[t];
    if (t == 1023) g_part[blockIdx.x] = sh[1023];
}
__global__ void scan_mid(int nb) {
    if (blockIdx.x == 0) {
        __shared__ int sh[128];
        int t = threadIdx.x;
        if (t < 128) {
            int v = (t < nb) ? g_part[t] : 0;
            sh[t] = v;
            __syncthreads();
            for (int o = 1; o < 128; o <<= 1) {
                int u = (t >= o) ? sh[t - o] : 0;
                __syncthreads();
                sh[t] += u;
                __syncthreads();
            }
            g_part[t] = sh[t] - v;   // exclusive
        }
    } else {
        __shared__ int sh[GMAX];
        int t = threadIdx.x;
        int v = g_gcnt[t];
        sh[t] = v;
        __syncthreads();
        for (int o = 1; o < GMAX; o <<= 1) {
            int u = (t >= o) ? sh[t - o] : 0;
            __syncthreads();
            sh[t] += u;
            __syncthreads();
        }
        g_goff[t] = sh[t] - v;   // exclusive
    }
}
__global__ void scan_finish(int n) {
    int i = blockIdx.x * 1024 + threadIdx.x;
    if (i < n) {
        int c = g_cnt[i];
        int off = g_part[i >> 10];
        int incl = g_incl[i] + off;
        int rp = incl - c;
        g_rowptr[i] = rp;
        g_wpos[i]   = rp;
        g_dinv[i]   = rsqrtf((float)(c + 1));   // +1 self-loop
        if (i == n - 1) g_rowptr[n] = incl;
    }
}
__global__ void place_edges(const int* __restrict__ ei, int E) {
    int e = blockIdx.x * blockDim.x + threadIdx.x;
    if (e < E) {
        int s = ei[e], d = ei[E + e];
        int pos = atomicAdd(&g_wpos[d], 1);
        g_srcs[pos] = s;
    }
}

// ---------------- fused layer: [BN+res+LN+GELU transform] + GEMM --------------
__global__ __launch_bounds__(256) void fused_layer(
    const float* __restrict__ xsrc,
    const float* __restrict__ pre,
    const float* __restrict__ bnsum, const float* __restrict__ bnsumsq,
    const float* __restrict__ bng, const float* __restrict__ bnb,
    const float* __restrict__ lng, const float* __restrict__ lnb,
    float* __restrict__ hio, int useRes,
    const float* __restrict__ W, float invN, int n) {
    __shared__ float Ws[64 * 64];      // [k][c]
    __shared__ float Hs[64][65];       // padded
    int t = threadIdx.x;
    for (int i = t; i < 1024; i += 256)
        ((float4*)Ws)[i] = ((const float4*)W)[i];
    int row0 = blockIdx.x * 64;

    if (pre == nullptr) {
        for (int i = t; i < 1024; i += 256) {
            int r = i >> 4, q = i & 15;
            int row = row0 + r;
            float4 v = (row < n) ? __ldg(&((const float4*)xsrc)[row * 16 + q])
                                 : make_float4(0.f, 0.f, 0.f, 0.f);
            Hs[r][q * 4 + 0] = v.x;
            Hs[r][q * 4 + 1] = v.y;
            Hs[r][q * 4 + 2] = v.z;
            Hs[r][q * 4 + 3] = v.w;
        }
    } else {
        int w = t >> 5, lane = t & 31;
        float mu0 = bnsum[lane] * invN;
        float var0 = bnsumsq[lane] * invN - mu0 * mu0;
        float sc0 = rsqrtf(var0 + 1e-5f) * bng[lane];
        float sh0 = bnb[lane] - mu0 * sc0;
        float mu1 = bnsum[lane + 32] * invN;
        float var1 = bnsumsq[lane + 32] * invN - mu1 * mu1;
        float sc1 = rsqrtf(var1 + 1e-5f) * bng[lane + 32];
        float sh1 = bnb[lane + 32] - mu1 * sc1;
        float lg0 = lng[lane], lb0 = lnb[lane];
        float lg1 = lng[lane + 32], lb1 = lnb[lane + 32];
#pragma unroll
        for (int rr = 0; rr < 8; rr++) {
            int r = w * 8 + rr;
            int row = row0 + r;
            if (row < n) {
                int i0 = row * 64 + lane, i1 = i0 + 32;
                float v0 = pre[i0] * sc0 + sh0;
                float v1 = pre[i1] * sc1 + sh1;
                if (useRes) { v0 += hio[i0]; v1 += hio[i1]; }
                float s = v0 + v1;
#pragma unroll
                for (int o = 16; o; o >>= 1) s += __shfl_xor_sync(0xffffffffu, s, o);
                float mu = s * (1.0f / 64.0f);
                float d0 = v0 - mu, d1 = v1 - mu;
                float vv = d0 * d0 + d1 * d1;
#pragma unroll
                for (int o = 16; o; o >>= 1) vv += __shfl_xor_sync(0xffffffffu, vv, o);
                float rstd = rsqrtf(vv * (1.0f / 64.0f) + 1e-5f);
                float y0 = gelu_exact(d0 * rstd * lg0 + lb0);
                float y1 = gelu_exact(d1 * rstd * lg1 + lb1);
                Hs[r][lane] = y0;
                Hs[r][lane + 32] = y1;
                hio[i0] = y0;
                hio[i1] = y1;
            } else {
                Hs[r][lane] = 0.f;
                Hs[r][lane + 32] = 0.f;
            }
        }
    }
    __syncthreads();

    int cq = (t & 15) * 4;
    int rb = (t >> 4) * 4;
    ull acc[4][2];
#pragma unroll
    for (int i = 0; i < 4; i++) { acc[i][0] = 0ull; acc[i][1] = 0ull; }
#pragma unroll 8
    for (int k = 0; k < 64; k++) {
        ull w01 = *(const ull*)&Ws[k * 64 + cq];
        ull w23 = *(const ull*)&Ws[k * 64 + cq + 2];
        ull h0 = pack2(Hs[rb + 0][k], Hs[rb + 0][k]);
        ull h1 = pack2(Hs[rb + 1][k], Hs[rb + 1][k]);
        ull h2 = pack2(Hs[rb + 2][k], Hs[rb + 2][k]);
        ull h3 = pack2(Hs[rb + 3][k], Hs[rb + 3][k]);
        ffma2(acc[0][0], h0, w01); ffma2(acc[0][1], h0, w23);
        ffma2(acc[1][0], h1, w01); ffma2(acc[1][1], h1, w23);
        ffma2(acc[2][0], h2, w01); ffma2(acc[2][1], h2, w23);
        ffma2(acc[3][0], h3, w01); ffma2(acc[3][1], h3, w23);
    }
#pragma unroll
    for (int i = 0; i < 4; i++) {
        int row = row0 + rb + i;
        if (row < n) {
            float di = g_dinv[row];
            float a0, a1, a2, a3;
            unpack2(acc[i][0], a0, a1);
            unpack2(acc[i][1], a2, a3);
            __half2 p01 = __floats2half2_rn(a0 * di, a1 * di);
            __half2 p23 = __floats2half2_rn(a2 * di, a3 * di);
            uint2 st;
            st.x = *(unsigned int*)&p01;
            st.y = *(unsigned int*)&p23;
            ((uint2*)g_hws2)[row * 16 + (cq >> 2)] = st;
        }
    }
}

// ---- CSR aggregate: 4 rows/warp, 8 lanes x 16B per row, + BN partials --------
__global__ __launch_bounds__(512) void aggregate(const float* __restrict__ convB,
                                                 float* __restrict__ bnsum,
                                                 float* __restrict__ bnsumsq,
                                                 int n) {
    __shared__ float bs[64], bs2[64];
    int t = threadIdx.x;
    if (t < 64) { bs[t] = 0.f; bs2[t] = 0.f; }
    __syncthreads();
    int warp = (blockIdx.x * 512 + t) >> 5;
    int lane = t & 31;
    int sub = lane & 7;           // lane within row (feature chunk)
    int group = lane >> 3;        // which of 4 rows
    int r = warp * 4 + group;
    float a[8];
#pragma unroll
    for (int j = 0; j < 8; j++) a[j] = 0.f;
    float psum[8], psq[8];
    bool valid = (r < n);
    if (valid) {
        acc8(((const uint4*)g_hws2)[r * 8 + sub], a);   // self-loop
        int p0 = g_rowptr[r], p1 = g_rowptr[r + 1];
#pragma unroll 4
        for (int p = p0; p < p1; p++) {
            int s = g_srcs[p];
            acc8(((const uint4*)g_hws2)[s * 8 + sub], a);
        }
        float di = g_dinv[r];
        float4 o0, o1;
        float* oo = &o0.x;
#pragma unroll
        for (int j = 0; j < 8; j++) {
            float pv = fmaf(di, a[j], convB[sub * 8 + j]);
            psum[j] = pv;
            psq[j] = pv * pv;
            if (j < 4) (&o0.x)[j] = pv; else (&o1.x)[j - 4] = pv;
        }
        (void)oo;
        ((float4*)g_pre)[r * 16 + sub * 2]     = o0;
        ((float4*)g_pre)[r * 16 + sub * 2 + 1] = o1;
    } else {
#pragma unroll
        for (int j = 0; j < 8; j++) { psum[j] = 0.f; psq[j] = 0.f; }
    }
    // butterfly across the 4 groups (lanes differing in bits 3,4)
#pragma unroll
    for (int j = 0; j < 8; j++) {
        psum[j] += __shfl_xor_sync(0xffffffffu, psum[j], 8);
        psq[j]  += __shfl_xor_sync(0xffffffffu, psq[j], 8);
        psum[j] += __shfl_xor_sync(0xffffffffu, psum[j], 16);
        psq[j]  += __shfl_xor_sync(0xffffffffu, psq[j], 16);
    }
    if (group == 0) {
#pragma unroll
        for (int j = 0; j < 8; j++) {
            atomicAdd(&bs[sub * 8 + j], psum[j]);
            atomicAdd(&bs2[sub * 8 + j], psq[j]);
        }
    }
    __syncthreads();
    if (t < 64) {
        atomicAdd(&bnsum[t], bs[t]);
        atomicAdd(&bnsumsq[t], bs2[t]);
    }
}

// ---- fused: final BN+res+LN+GELU transform + pool + MLP head per graph -------
__global__ __launch_bounds__(256) void pool_mlp(
    const float* __restrict__ bnsum, const float* __restrict__ bnsumsq,
    const float* __restrict__ bng, const float* __restrict__ bnb,
    const float* __restrict__ lng, const float* __restrict__ lnb,
    const float* __restrict__ W1, const float* __restrict__ b1,
    const float* __restrict__ l1g, const float* __restrict__ l1b,
    const float* __restrict__ W2, const float* __restrict__ b2,
    const float* __restrict__ l2g, const float* __restrict__ l2b,
    const float* __restrict__ W3, const float* __restrict__ b3,
    float* __restrict__ out, float invN) {
    int g = blockIdx.x, t = threadIdx.x;   // 256 threads = 8 warps
    __shared__ float zs[192];
    __shared__ float shs[8][64], shm[8][64];
    __shared__ float s2[128];
    __shared__ float red[128];

    int start = g_goff[g], cnt = g_gcnt[g];
    int w = t >> 5, lane = t & 31;

    // layer-2 BN constants for features lane, lane+32
    float mu0 = bnsum[lane] * invN;
    float var0 = bnsumsq[lane] * invN - mu0 * mu0;
    float sc0 = rsqrtf(var0 + 1e-5f) * bng[lane];
    float sh0 = bnb[lane] - mu0 * sc0;
    float mu1 = bnsum[lane + 32] * invN;
    float var1 = bnsumsq[lane + 32] * invN - mu1 * mu1;
    float sc1 = rsqrtf(var1 + 1e-5f) * bng[lane + 32];
    float sh1 = bnb[lane + 32] - mu1 * sc1;
    float lg0 = lng[lane], lb0 = lnb[lane];
    float lg1 = lng[lane + 32], lb1 = lnb[lane + 32];

    float s0 = 0.f, s1 = 0.f, m0 = -FLT_MAX, m1 = -FLT_MAX;
    for (int r = start + w; r < start + cnt; r += 8) {
        int i0 = r * 64 + lane, i1 = i0 + 32;
        float v0 = g_pre[i0] * sc0 + sh0 + g_h[i0];
        float v1 = g_pre[i1] * sc1 + sh1 + g_h[i1];
        float s = v0 + v1;
#pragma unroll
        for (int o = 16; o; o >>= 1) s += __shfl_xor_sync(0xffffffffu, s, o);
        float mu = s * (1.0f / 64.0f);
        float d0 = v0 - mu, d1 = v1 - mu;
        float vv = d0 * d0 + d1 * d1;
#pragma unroll
        for (int o = 16; o; o >>= 1) vv += __shfl_xor_sync(0xffffffffu, vv, o);
        float rstd = rsqrtf(vv * (1.0f / 64.0f) + 1e-5f);
        float y0 = gelu_exact(d0 * rstd * lg0 + lb0);
        float y1 = gelu_exact(d1 * rstd * lg1 + lb1);
        s0 += y0; s1 += y1;
        m0 = fmaxf(m0, y0); m1 = fmaxf(m1, y1);
    }
    shs[w][lane] = s0; shs[w][lane + 32] = s1;
    shm[w][lane] = m0; shm[w][lane + 32] = m1;
    __syncthreads();
    if (t < 64) {
        float s = 0.f, m = -FLT_MAX;
#pragma unroll
        for (int k = 0; k < 8; k++) {
            s += shs[k][t];
            m = fmaxf(m, shm[k][t]);
        }
        float mean = (cnt > 0) ? s / (float)cnt : 0.f;
        if (cnt == 0) { m = 0.f; s = 0.f; }
        zs[t] = mean;
        zs[64 + t] = m;
        zs[128 + t] = s;
    }
    __syncthreads();

    // ---- MLP phase (first 128 threads) ----
    float accv = 0.f;
    if (t < 128) {
        accv = b1[t];
#pragma unroll 4
        for (int k = 0; k < 192; k++) accv = fmaf(zs[k], W1[k * 128 + t], accv);
        red[t] = accv;
    }
    __syncthreads();
    if (t < 128) {
        for (int o = 64; o > 0; o >>= 1) {
            if (t < o) red[t] += red[t + o];
            __syncwarp(0xffffffffu);
            if (o > 32) __syncthreads();
        }
    }
    __syncthreads();
    float mu = red[0] * (1.0f / 128.0f);
    __syncthreads();
    float dv = accv - mu;
    if (t < 128) red[t] = dv * dv;
    __syncthreads();
    if (t < 128) {
        for (int o = 64; o > 0; o >>= 1) {
            if (t < o) red[t] += red[t + o];
            __syncwarp(0xffffffffu);
            if (o > 32) __syncthreads();
        }
    }
    __syncthreads();
    float rstd = rsqrtf(red[0] * (1.0f / 128.0f) + 1e-5f);
    __syncthreads();
    if (t < 128) s2[t] = gelu_exact(dv * rstd * l1g[t] + l1b[t]);
    __syncthreads();
    // layer 2: 128 -> 64
    float acc2 = 0.f;
    if (t < 64) {
        acc2 = b2[t];
#pragma unroll 4
        for (int k = 0; k < 128; k++) acc2 = fmaf(s2[k], W2[k * 64 + t], acc2);
    }
    if (t < 128) red[t] = (t < 64) ? acc2 : 0.f;
    __syncthreads();
    if (t < 128) {
        for (int o = 64; o > 0; o >>= 1) {
            if (t < o) red[t] += red[t + o];
            __syncwarp(0xffffffffu);
            if (o > 32) __syncthreads();
        }
    }
    __syncthreads();
    float mu2 = red[0] * (1.0f / 64.0f);
    __syncthreads();
    float dv2 = acc2 - mu2;
    if (t < 128) red[t] = (t < 64) ? dv2 * dv2 : 0.f;
    __syncthreads();
    if (t < 128) {
        for (int o = 64; o > 0; o >>= 1) {
            if (t < o) red[t] += red[t + o];
            __syncwarp(0xffffffffu);
            if (o > 32) __syncthreads();
        }
    }
    __syncthreads();
    float rstd2 = rsqrtf(red[0] * (1.0f / 64.0f) + 1e-5f);
    __syncthreads();
    float y2 = 0.f;
    if (t < 64) y2 = gelu_exact(dv2 * rstd2 * l2g[t] + l2b[t]);
    if (t < 128) red[t] = (t < 64) ? y2 * W3[t] : 0.f;
    __syncthreads();
    if (t < 128) {
        for (int o = 64; o > 0; o >>= 1) {
            if (t < o) red[t] += red[t + o];
            __syncwarp(0xffffffffu);
            if (o > 32) __syncthreads();
        }
    }
    __syncthreads();
    if (t == 0) out[g] = red[0] + b3[0];
}

// ---------------- host ----------------
extern "C" void kernel_launch(void* const* d_in, const int* in_sizes, int n_in,
                              void* d_out, int out_size) {
    const float* x     = (const float*)d_in[0];
    const int*   ei    = (const int*)d_in[1];
    const int*   batch = (const int*)d_in[2];
    const float* convW = (const float*)d_in[3];
    const float* convB = (const float*)d_in[4];
    const float* bn_g  = (const float*)d_in[5];
    const float* bn_b  = (const float*)d_in[6];
    const float* ln_g  = (const float*)d_in[7];
    const float* ln_b  = (const float*)d_in[8];
    const float* W1    = (const float*)d_in[9];
    const float* b1    = (const float*)d_in[10];
    const float* l1g   = (const float*)d_in[11];
    const float* l1b   = (const float*)d_in[12];
    const float* W2    = (const float*)d_in[13];
    const float* b2    = (const float*)d_in[14];
    const float* l2g   = (const float*)d_in[15];
    const float* l2b   = (const float*)d_in[16];
    const float* W3    = (const float*)d_in[17];
    const float* b3    = (const float*)d_in[18];
    float* out = (float*)d_out;

    const int N = in_sizes[0] / 64;
    const int E = in_sizes[1] / 2;
    const int G = out_size;          // 512
    const float invN = 1.0f / (float)N;

    float* p_h; float* p_pre; float* p_bnsum; float* p_bnsumsq;
    cudaGetSymbolAddress((void**)&p_h,       g_h);
    cudaGetSymbolAddress((void**)&p_pre,     g_pre);
    cudaGetSymbolAddress((void**)&p_bnsum,   g_bnsum);
    cudaGetSymbolAddress((void**)&p_bnsumsq, g_bnsumsq);

    const int TB = 256;
    setup_zero<<<(N + TB - 1) / TB, TB>>>(N, G);
    hist_both<<<(E + N + TB - 1) / TB, TB>>>(ei, batch, E, N);
    int nb = (N + 1023) / 1024;
    scan_blocks<<<nb, 1024>>>(N);
    scan_mid<<<2, 512>>>(nb);
    scan_finish<<<nb, 1024>>>(N);
    place_edges<<<(E + TB - 1) / TB, TB>>>(ei, E);

    int fgrid = (N + 63) / 64;
    int agrid = (N + 63) / 64;   // 4 rows/warp, 16 warps/block -> 64 rows/block

    // layer 0 gemm (raw x input)
    fused_layer<<<fgrid, 256>>>(x, nullptr, nullptr, nullptr, nullptr, nullptr,
                                nullptr, nullptr, p_h, 0, convW, invN, N);
    aggregate<<<agrid, 512>>>(convB, p_bnsum, p_bnsumsq, N);

    // layer 1: transform layer-0 output (no residual) + gemm W1
    fused_layer<<<fgrid, 256>>>(nullptr, p_pre, p_bnsum, p_bnsumsq,
                                bn_g, bn_b, ln_g, ln_b,
                                p_h, 0, convW + 64 * 64, invN, N);
    aggregate<<<agrid, 512>>>(convB + 64, p_bnsum + 64, p_bnsumsq + 64, N);

    // layer 2: transform layer-1 output (residual) + gemm W2
    fused_layer<<<fgrid, 256>>>(nullptr, p_pre, p_bnsum + 64, p_bnsumsq + 64,
                                bn_g + 64, bn_b + 64, ln_g + 64, ln_b + 64,
                                p_h, 1, convW + 2 * 64 * 64, invN, N);
    aggregate<<<agrid, 512>>>(convB + 2 * 64, p_bnsum + 2 * 64, p_bnsumsq + 2 * 64, N);

    // final transform fused into pool + MLP
    pool_mlp<<<G, 256>>>(p_bnsum + 2 * 64, p_bnsumsq + 2 * 64,
                         bn_g + 2 * 64, bn_b + 2 * 64,
                         ln_g + 2 * 64, ln_b + 2 * 64,
                         W1, b1, l1g, l1b, W2, b2, l2g, l2b, W3, b3, out, invN);
}